// round 2
// baseline (speedup 1.0000x reference)
#include <cuda_runtime.h>
#include <math.h>

#define B_  4
#define T_  2048
#define E_  1024
#define H_  16
#define D_  64
#define CH  128
#define NC  (T_/CH)      // 16
#define M_  (B_*T_)      // 8192
#define EPS 1e-6f

// ---------------- scratch (no allocations allowed) ----------------
__device__ float g_q[M_*E_];
__device__ float g_k[M_*E_];
__device__ float g_v[M_*E_];
__device__ float g_y[M_*E_];
__device__ float g_kv[B_*H_*NC*D_*D_];
__device__ float g_zk[B_*H_*NC*D_];
__device__ float g_S [B_*H_*NC*D_*D_];
__device__ float g_Z [B_*H_*NC*D_];

// =================================================================
// GEMM: C[m,n] = act( sum_k A[m,k] * W[n,k] + bias[n] )
// M x N x K, tiles 128x128x16, 256 threads, 8x8 per thread.
// ACT: 0 = none, 1 = elu(x)+1
// =================================================================
template<int ACT, int BIAS>
__global__ __launch_bounds__(256)
void gemm_kernel(const float* __restrict__ A, const float* __restrict__ W,
                 const float* __restrict__ bias, float* __restrict__ C,
                 int M, int N, int K)
{
    __shared__ float As[16*128];
    __shared__ float Bs[16*128];

    const int tid = threadIdx.x;
    const int tx  = tid & 15;
    const int ty  = tid >> 4;
    const int m0  = blockIdx.y * 128;
    const int n0  = blockIdx.x * 128;

    float acc[8][8];
#pragma unroll
    for (int i = 0; i < 8; i++)
#pragma unroll
        for (int j = 0; j < 8; j++) acc[i][j] = 0.f;

    for (int k0 = 0; k0 < K; k0 += 16) {
        // 128 rows x 16 k = 512 float4 total (A and W each)
#pragma unroll
        for (int it = 0; it < 2; it++) {
            int idx4 = tid + it * 256;        // 0..511
            int row  = idx4 >> 2;             // 4 float4 per row (16 k)
            int kc   = (idx4 & 3) << 2;
            float4 va = *(const float4*)&A[(size_t)(m0 + row) * K + k0 + kc];
            As[(kc+0)*128 + row] = va.x;
            As[(kc+1)*128 + row] = va.y;
            As[(kc+2)*128 + row] = va.z;
            As[(kc+3)*128 + row] = va.w;
            float4 vb = *(const float4*)&W[(size_t)(n0 + row) * K + k0 + kc];
            Bs[(kc+0)*128 + row] = vb.x;
            Bs[(kc+1)*128 + row] = vb.y;
            Bs[(kc+2)*128 + row] = vb.z;
            Bs[(kc+3)*128 + row] = vb.w;
        }
        __syncthreads();

#pragma unroll
        for (int kk = 0; kk < 16; kk++) {
            float af[8], bf[8];
            *(float4*)&af[0] = *(const float4*)&As[kk*128 + ty*8];
            *(float4*)&af[4] = *(const float4*)&As[kk*128 + ty*8 + 4];
            *(float4*)&bf[0] = *(const float4*)&Bs[kk*128 + tx*8];
            *(float4*)&bf[4] = *(const float4*)&Bs[kk*128 + tx*8 + 4];
#pragma unroll
            for (int i = 0; i < 8; i++)
#pragma unroll
                for (int j = 0; j < 8; j++)
                    acc[i][j] += af[i] * bf[j];
        }
        __syncthreads();
    }

#pragma unroll
    for (int i = 0; i < 8; i++) {
        int m = m0 + ty*8 + i;
#pragma unroll
        for (int j0 = 0; j0 < 8; j0 += 4) {
            float4 o;
            float vals[4];
#pragma unroll
            for (int j = 0; j < 4; j++) {
                float v = acc[i][j0 + j];
                if (BIAS) v += bias[n0 + tx*8 + j0 + j];
                if (ACT)  v = (v > 0.f) ? (v + 1.f) : expf(v);
                vals[j] = v;
            }
            o.x = vals[0]; o.y = vals[1]; o.z = vals[2]; o.w = vals[3];
            *(float4*)&C[(size_t)m * N + n0 + tx*8 + j0] = o;
        }
    }
}

// =================================================================
// kv/zk per chunk: kv[d,e] = sum_c phi_k[c,d]*v[c,e]; zk[d]=sum_c phi_k[c,d]
// one block per (b,h,n); 256 threads; dynamic smem (2 x 128x68)
// =================================================================
__global__ __launch_bounds__(256)
void kv_kernel(const float* __restrict__ k, const float* __restrict__ v,
               float* __restrict__ kv, float* __restrict__ zk)
{
    extern __shared__ float sm[];
    float* sk = sm;              // 128*68
    float* sv = sm + 128*68;     // 128*68

    const int bid = blockIdx.x;                // = ((b*H+h)*NC + n)
    const int n = bid % NC;
    const int h = (bid / NC) % H_;
    const int b = bid / (NC * H_);
    const int tid = threadIdx.x;

    const float* kb = k + (size_t)(b*T_ + n*CH) * E_ + h*D_;
    const float* vb = v + (size_t)(b*T_ + n*CH) * E_ + h*D_;

    // 128 rows x 64 cols = 2048 float4 (each of sk, sv)
#pragma unroll
    for (int it = 0; it < 8; it++) {
        int idx4 = tid + it * 256;   // 0..2047
        int c  = idx4 >> 4;          // 0..127
        int d0 = (idx4 & 15) << 2;   // 0..60
        *(float4*)&sk[c*68 + d0] = *(const float4*)&kb[(size_t)c * E_ + d0];
        *(float4*)&sv[c*68 + d0] = *(const float4*)&vb[(size_t)c * E_ + d0];
    }
    __syncthreads();

    const int tx = tid & 15, ty = tid >> 4;
    float acc[4][4];
#pragma unroll
    for (int i = 0; i < 4; i++)
#pragma unroll
        for (int j = 0; j < 4; j++) acc[i][j] = 0.f;

#pragma unroll 8
    for (int c = 0; c < 128; c++) {
        float4 kf = *(const float4*)&sk[c*68 + ty*4];
        float4 vf = *(const float4*)&sv[c*68 + tx*4];
        float ka[4] = {kf.x, kf.y, kf.z, kf.w};
        float va[4] = {vf.x, vf.y, vf.z, vf.w};
#pragma unroll
        for (int i = 0; i < 4; i++)
#pragma unroll
            for (int j = 0; j < 4; j++)
                acc[i][j] += ka[i] * va[j];
    }

    float* kvb = kv + (size_t)bid * (D_*D_);
#pragma unroll
    for (int i = 0; i < 4; i++) {
        float4 o = {acc[i][0], acc[i][1], acc[i][2], acc[i][3]};
        *(float4*)&kvb[(ty*4 + i) * D_ + tx*4] = o;
    }

    if (tid < D_) {
        float s = 0.f;
        for (int c = 0; c < 128; c++) s += sk[c*68 + tid];
        zk[(size_t)bid * D_ + tid] = s;
    }
}

// =================================================================
// exclusive prefix over chunks (N=16) per (b,h)
// =================================================================
__global__ __launch_bounds__(256)
void prefix_kernel(const float* __restrict__ kv, const float* __restrict__ zk,
                   float* __restrict__ S, float* __restrict__ Z)
{
    const int bh = blockIdx.x;     // 0..B*H-1
    const size_t base = (size_t)bh * NC * (D_*D_);
    for (int i = threadIdx.x; i < D_*D_; i += blockDim.x) {
        float run = 0.f;
        for (int n = 0; n < NC; n++) {
            S[base + (size_t)n * (D_*D_) + i] = run;
            run += kv[base + (size_t)n * (D_*D_) + i];
        }
    }
    const size_t zb = (size_t)bh * NC * D_;
    for (int i = threadIdx.x; i < D_; i += blockDim.x) {
        float run = 0.f;
        for (int n = 0; n < NC; n++) {
            Z[zb + (size_t)n * D_ + i] = run;
            run += zk[zb + (size_t)n * D_ + i];
        }
    }
}

// =================================================================
// intra-chunk attention; one block per (b,h,n); 256 threads
// smem layout (floats):
//   sqT  [64][128]    off 0      (phi_q transposed: [d][c])
//   skv             off 8192     (first phi_k^T [64][128], then v [128][68])
//   sAT  [128][132] off 16896    (A transposed: [s][c], masked)
//   sS   [64][68]   off 33792
//   sZ   [64]       off 38144
//   sden [128]      off 38208
// total 38336 floats = 153344 B
// =================================================================
#define ATTN_SMEM_FLOATS 38336
__global__ __launch_bounds__(256)
void attn_kernel(const float* __restrict__ q, const float* __restrict__ k,
                 const float* __restrict__ v, const float* __restrict__ S,
                 const float* __restrict__ Z, float* __restrict__ y)
{
    extern __shared__ float sm[];
    float* sqT  = sm;
    float* skv  = sm + 8192;
    float* sAT  = sm + 16896;
    float* sS   = sm + 33792;
    float* sZ   = sm + 38144;
    float* sden = sm + 38208;

    const int bid = blockIdx.x;
    const int n = bid % NC;
    const int h = (bid / NC) % H_;
    const int b = bid / (NC * H_);
    const int tid = threadIdx.x, tx = tid & 15, ty = tid >> 4;

    const float* qb = q + (size_t)(b*T_ + n*CH) * E_ + h*D_;
    const float* kb = k + (size_t)(b*T_ + n*CH) * E_ + h*D_;
    const float* vb = v + (size_t)(b*T_ + n*CH) * E_ + h*D_;
    const float* Sb = S + (size_t)bid * (D_*D_);
    const float* Zb = Z + (size_t)bid * D_;

    // ---- phase 1: load phi_q, phi_k transposed (128 rows x 64 = 2048 float4 each) ----
#pragma unroll
    for (int it = 0; it < 8; it++) {
        int idx4 = tid + it * 256;   // 0..2047
        int c  = idx4 >> 4;          // 0..127
        int d0 = (idx4 & 15) << 2;   // 0..60
        float4 vq = *(const float4*)&qb[(size_t)c * E_ + d0];
        sqT[(d0+0)*128 + c] = vq.x;
        sqT[(d0+1)*128 + c] = vq.y;
        sqT[(d0+2)*128 + c] = vq.z;
        sqT[(d0+3)*128 + c] = vq.w;
        float4 vk = *(const float4*)&kb[(size_t)c * E_ + d0];
        skv[(d0+0)*128 + c] = vk.x;
        skv[(d0+1)*128 + c] = vk.y;
        skv[(d0+2)*128 + c] = vk.z;
        skv[(d0+3)*128 + c] = vk.w;
    }
    __syncthreads();

    // ---- phase 2: A = phi_q phi_k^T (8x8 per thread), mask, store transposed ----
    float acc[8][8];
#pragma unroll
    for (int i = 0; i < 8; i++)
#pragma unroll
        for (int j = 0; j < 8; j++) acc[i][j] = 0.f;

#pragma unroll 8
    for (int kk = 0; kk < 64; kk++) {
        float af[8], bf[8];
        *(float4*)&af[0] = *(const float4*)&sqT[kk*128 + ty*8];
        *(float4*)&af[4] = *(const float4*)&sqT[kk*128 + ty*8 + 4];
        *(float4*)&bf[0] = *(const float4*)&skv[kk*128 + tx*8];
        *(float4*)&bf[4] = *(const float4*)&skv[kk*128 + tx*8 + 4];
#pragma unroll
        for (int i = 0; i < 8; i++)
#pragma unroll
            for (int j = 0; j < 8; j++)
                acc[i][j] += af[i] * bf[j];
    }

    const int c0 = ty*8, s0 = tx*8;
#pragma unroll
    for (int j = 0; j < 8; j++) {
        int s = s0 + j;
#pragma unroll
        for (int i = 0; i < 8; i++)
            if (s > c0 + i) acc[i][j] = 0.f;
        float4 t0 = {acc[0][j], acc[1][j], acc[2][j], acc[3][j]};
        *(float4*)&sAT[s*132 + c0] = t0;
        float4 t1 = {acc[4][j], acc[5][j], acc[6][j], acc[7][j]};
        *(float4*)&sAT[s*132 + c0 + 4] = t1;
    }
    __syncthreads();

    // ---- phase 3: load v (row-major, 2048 float4), S_prev, Z_prev ----
#pragma unroll
    for (int it = 0; it < 8; it++) {
        int idx4 = tid + it * 256;   // 0..2047
        int c  = idx4 >> 4;          // 0..127
        int e0 = (idx4 & 15) << 2;
        *(float4*)&skv[c*68 + e0] = *(const float4*)&vb[(size_t)c * E_ + e0];
    }
#pragma unroll
    for (int it = 0; it < 4; it++) {
        int idx4 = tid + it * 256;   // 1024 float4 = 64x64
        int d  = idx4 >> 4;
        int e0 = (idx4 & 15) << 2;
        *(float4*)&sS[d*68 + e0] = *(const float4*)&Sb[d*D_ + e0];
    }
    if (tid < 16)
        *(float4*)&sZ[tid*4] = *(const float4*)&Zb[tid*4];
    __syncthreads();

    // ---- phase 4: denominator ----
    if (tid < 128) {
        float s = EPS;
        for (int ss = 0; ss < 128; ss++) s += sAT[ss*132 + tid];
        for (int d = 0; d < 64; d++)     s += sqT[d*128 + tid] * sZ[d];
        sden[tid] = s;
    }
    __syncthreads();

    // ---- phase 5: num = A@v + phi_q@S_prev, divide, write ----
    float num[8][4];
#pragma unroll
    for (int i = 0; i < 8; i++)
#pragma unroll
        for (int j = 0; j < 4; j++) num[i][j] = 0.f;

#pragma unroll 8
    for (int ss = 0; ss < 128; ss++) {
        float af[8];
        *(float4*)&af[0] = *(const float4*)&sAT[ss*132 + ty*8];
        *(float4*)&af[4] = *(const float4*)&sAT[ss*132 + ty*8 + 4];
        float4 vf = *(const float4*)&skv[ss*68 + tx*4];
        float vv[4] = {vf.x, vf.y, vf.z, vf.w};
#pragma unroll
        for (int i = 0; i < 8; i++)
#pragma unroll
            for (int j = 0; j < 4; j++)
                num[i][j] += af[i] * vv[j];
    }
#pragma unroll 8
    for (int d = 0; d < 64; d++) {
        float af[8];
        *(float4*)&af[0] = *(const float4*)&sqT[d*128 + ty*8];
        *(float4*)&af[4] = *(const float4*)&sqT[d*128 + ty*8 + 4];
        float4 sf = *(const float4*)&sS[d*68 + tx*4];
        float svv[4] = {sf.x, sf.y, sf.z, sf.w};
#pragma unroll
        for (int i = 0; i < 8; i++)
#pragma unroll
            for (int j = 0; j < 4; j++)
                num[i][j] += af[i] * svv[j];
    }

    float* yb = y + (size_t)(b*T_ + n*CH) * E_ + h*D_;
#pragma unroll
    for (int i = 0; i < 8; i++) {
        int c = ty*8 + i;
        float inv = 1.f / sden[c];
        float4 o = {num[i][0]*inv, num[i][1]*inv, num[i][2]*inv, num[i][3]*inv};
        *(float4*)&yb[(size_t)c * E_ + tx*4] = o;
    }
}

// =================================================================
extern "C" void kernel_launch(void* const* d_in, const int* in_sizes, int n_in,
                              void* d_out, int out_size)
{
    const float* x  = (const float*)d_in[0];
    const float* Wq = (const float*)d_in[1];
    const float* Wk = (const float*)d_in[2];
    const float* Wv = (const float*)d_in[3];
    const float* Wp = (const float*)d_in[4];
    const float* bp = (const float*)d_in[5];
    float* out = (float*)d_out;

    float *q, *k, *v, *y, *kv, *zk, *S, *Z;
    cudaGetSymbolAddress((void**)&q,  g_q);
    cudaGetSymbolAddress((void**)&k,  g_k);
    cudaGetSymbolAddress((void**)&v,  g_v);
    cudaGetSymbolAddress((void**)&y,  g_y);
    cudaGetSymbolAddress((void**)&kv, g_kv);
    cudaGetSymbolAddress((void**)&zk, g_zk);
    cudaGetSymbolAddress((void**)&S,  g_S);
    cudaGetSymbolAddress((void**)&Z,  g_Z);

    const int kv_smem   = 2 * 128 * 68 * (int)sizeof(float);     // 69632
    const int attn_smem = ATTN_SMEM_FLOATS * (int)sizeof(float); // 153344
    cudaFuncSetAttribute(kv_kernel,  cudaFuncAttributeMaxDynamicSharedMemorySize, kv_smem);
    cudaFuncSetAttribute(attn_kernel, cudaFuncAttributeMaxDynamicSharedMemorySize, attn_smem);

    dim3 blk(256);
    dim3 gg(E_/128, M_/128);

    gemm_kernel<1,0><<<gg, blk>>>(x, Wq, nullptr, q, M_, E_, E_);
    gemm_kernel<1,0><<<gg, blk>>>(x, Wk, nullptr, k, M_, E_, E_);
    gemm_kernel<0,0><<<gg, blk>>>(x, Wv, nullptr, v, M_, E_, E_);

    kv_kernel<<<B_*H_*NC, blk, kv_smem>>>(k, v, kv, zk);
    prefix_kernel<<<B_*H_, blk>>>(kv, zk, S, Z);
    attn_kernel<<<B_*H_*NC, blk, attn_smem>>>(q, k, v, S, Z, y);

    gemm_kernel<0,1><<<gg, blk>>>(y, Wp, bp, out, M_, E_, E_);
}

// round 6
// speedup vs baseline: 2.5196x; 2.5196x over previous
#include <cuda_runtime.h>
#include <math.h>
#include <stdint.h>

#define B_  4
#define T_  2048
#define E_  1024
#define H_  16
#define D_  64
#define CH  128
#define NC  (T_/CH)      // 16
#define M_  (B_*T_)      // 8192
#define EPS 1e-6f

// ---------------- scratch (no allocations allowed) ----------------
__device__ float g_q[M_*E_];
__device__ float g_k[M_*E_];
__device__ float g_v[M_*E_];
__device__ float g_y[M_*E_];
__device__ float g_kv[B_*H_*NC*D_*D_];
__device__ float g_zk[B_*H_*NC*D_];
__device__ float g_S [B_*H_*NC*D_*D_];
__device__ float g_Z [B_*H_*NC*D_];

// =================================================================
// helpers
// =================================================================
__device__ __forceinline__ uint32_t smem_u32(const void* p){
    uint32_t a;
    asm("{ .reg .u64 t; cvta.to.shared.u64 t, %1; cvt.u32.u64 %0, t; }" : "=r"(a) : "l"(p));
    return a;
}
__device__ __forceinline__ void cpasync16(uint32_t dst, const void* src){
    asm volatile("cp.async.cg.shared.global [%0], [%1], 16;" :: "r"(dst), "l"(src));
}
__device__ __forceinline__ void cp_commit(){ asm volatile("cp.async.commit_group;" ::: "memory"); }
__device__ __forceinline__ void cp_wait1(){ asm volatile("cp.async.wait_group 1;" ::: "memory"); }

__device__ __forceinline__ uint32_t f2tf32(float v){
    uint32_t u;
    asm("cvt.rna.tf32.f32 %0, %1;" : "=r"(u) : "f"(v));
    return u;
}
__device__ __forceinline__ void mma_tf32_16x8x8(float* c, const uint32_t* a, const uint32_t* b){
    asm volatile(
        "mma.sync.aligned.m16n8k8.row.col.f32.tf32.tf32.f32 "
        "{%0,%1,%2,%3}, {%4,%5,%6,%7}, {%8,%9}, {%0,%1,%2,%3};"
        : "+f"(c[0]), "+f"(c[1]), "+f"(c[2]), "+f"(c[3])
        : "r"(a[0]), "r"(a[1]), "r"(a[2]), "r"(a[3]), "r"(b[0]), "r"(b[1]));
}

// =================================================================
// tf32 mma.sync GEMM: C[m,n] = act( sum_k A[m,k]*W[n,k] + bias[n] )
// tile 128x128, K chunks of 32, 3-stage cp.async pipeline.
// 8 warps as 4(m) x 2(n); warp tile 32x64 -> 2 m-frags x 8 n-frags.
// smem: padded stride 36 floats -> conflict-free fragment loads.
// =================================================================
#define TM 128
#define TN 128
#define TK 32
#define NS 3
#define NCHUNK (E_/TK)                    // 32
#define ROWF 36                           // padded row stride (floats)
#define TILE_FLOATS (128*ROWF)            // 4608
#define STAGE_FLOATS (2*TILE_FLOATS)      // A then W
#define GEMM_SMEM (NS*STAGE_FLOATS*4)     // 110592 bytes

__device__ __forceinline__ void load_chunk(const float* __restrict__ A,
                                           const float* __restrict__ W, int K,
                                           int m0, int n0, int k0,
                                           uint32_t sA, uint32_t sW, int tid){
#pragma unroll
    for (int it = 0; it < 4; it++){
        int idx = tid + it*256;            // 0..1023
        int row = idx >> 3;                // 0..127
        int kq  = idx & 7;                 // float4 within the 32-float k-chunk
        uint32_t soff = (row*ROWF + kq*4) * 4;
        cpasync16(sA + soff, A + (size_t)(m0+row)*K + k0 + kq*4);
        cpasync16(sW + soff, W + (size_t)(n0+row)*K + k0 + kq*4);
    }
}

template<int ACT, int BIAS>
__global__ __launch_bounds__(256)
void tc_gemm(const float* __restrict__ A, const float* __restrict__ W,
             const float* __restrict__ bias, float* __restrict__ C,
             int M, int N, int K)
{
    extern __shared__ float sm[];
    const int tid = threadIdx.x;
    const int wid = tid >> 5, lane = tid & 31;
    const int m0 = blockIdx.y * TM, n0 = blockIdx.x * TN;
    const int mw0 = (wid >> 1) * 32;       // warp m-offset in tile
    const int nw0 = (wid & 1) * 64;        // warp n-offset in tile
    const int r  = lane >> 2;              // 0..7
    const int cq = lane & 3;               // 0..3
    const uint32_t sb = smem_u32(sm);

    float acc[2][8][4];
#pragma unroll
    for (int mi = 0; mi < 2; mi++)
#pragma unroll
        for (int ni = 0; ni < 8; ni++)
#pragma unroll
            for (int j = 0; j < 4; j++) acc[mi][ni][j] = 0.f;

    // prologue: stages 0,1
#pragma unroll
    for (int c = 0; c < NS-1; c++){
        uint32_t st = sb + c*STAGE_FLOATS*4;
        load_chunk(A, W, K, m0, n0, c*TK, st, st + TILE_FLOATS*4, tid);
        cp_commit();
    }

    for (int c = 0; c < NCHUNK; c++){
        cp_wait1();
        __syncthreads();
        if (c + 2 < NCHUNK){
            uint32_t st = sb + ((c+2)%NS)*STAGE_FLOATS*4;
            load_chunk(A, W, K, m0, n0, (c+2)*TK, st, st + TILE_FLOATS*4, tid);
        }
        cp_commit();

        const float* fa = sm + (c%NS)*STAGE_FLOATS;
        const float* fw = fa + TILE_FLOATS;

#pragma unroll
        for (int ks = 0; ks < 4; ks++){
            const int kb = ks*8;
            uint32_t afr[2][4];
#pragma unroll
            for (int mi = 0; mi < 2; mi++){
                const float* ap = fa + (mw0 + mi*16 + r)*ROWF + kb + cq;
                afr[mi][0] = f2tf32(ap[0]);
                afr[mi][1] = f2tf32(ap[8*ROWF]);
                afr[mi][2] = f2tf32(ap[4]);
                afr[mi][3] = f2tf32(ap[8*ROWF + 4]);
            }
#pragma unroll
            for (int ni = 0; ni < 8; ni++){
                uint32_t bfr[2];
                const float* bp = fw + (nw0 + ni*8 + r)*ROWF + kb + cq;
                bfr[0] = f2tf32(bp[0]);
                bfr[1] = f2tf32(bp[4]);
#pragma unroll
                for (int mi = 0; mi < 2; mi++)
                    mma_tf32_16x8x8(acc[mi][ni], afr[mi], bfr);
            }
        }
        __syncthreads();
    }

    // epilogue: c0,c1 -> (row, col..col+1); c2,c3 -> (row+8, ...)
#pragma unroll
    for (int mi = 0; mi < 2; mi++){
#pragma unroll
        for (int ni = 0; ni < 8; ni++){
            const int row = m0 + mw0 + mi*16 + r;
            const int col = n0 + nw0 + ni*8 + cq*2;
            float v[4];
#pragma unroll
            for (int j = 0; j < 4; j++){
                float x = acc[mi][ni][j];
                if (BIAS) x += bias[col + (j & 1)];
                if (ACT)  x = (x > 0.f) ? (x + 1.f) : expf(x);
                v[j] = x;
            }
            float2 lo = {v[0], v[1]}, hi = {v[2], v[3]};
            *(float2*)&C[(size_t)row * N + col]       = lo;
            *(float2*)&C[(size_t)(row+8) * N + col]   = hi;
        }
    }
}

// =================================================================
// kv/zk per chunk: kv[d,e] = sum_c phi_k[c,d]*v[c,e]; zk[d]=sum_c phi_k[c,d]
// =================================================================
__global__ __launch_bounds__(256)
void kv_kernel(const float* __restrict__ k, const float* __restrict__ v,
               float* __restrict__ kv, float* __restrict__ zk)
{
    extern __shared__ float sm[];
    float* sk = sm;              // 128*68
    float* sv = sm + 128*68;     // 128*68

    const int bid = blockIdx.x;
    const int n = bid % NC;
    const int h = (bid / NC) % H_;
    const int b = bid / (NC * H_);
    const int tid = threadIdx.x;

    const float* kb = k + (size_t)(b*T_ + n*CH) * E_ + h*D_;
    const float* vb = v + (size_t)(b*T_ + n*CH) * E_ + h*D_;

#pragma unroll
    for (int it = 0; it < 8; it++) {
        int idx4 = tid + it * 256;
        int c  = idx4 >> 4;
        int d0 = (idx4 & 15) << 2;
        *(float4*)&sk[c*68 + d0] = *(const float4*)&kb[(size_t)c * E_ + d0];
        *(float4*)&sv[c*68 + d0] = *(const float4*)&vb[(size_t)c * E_ + d0];
    }
    __syncthreads();

    const int tx = tid & 15, ty = tid >> 4;
    float acc[4][4];
#pragma unroll
    for (int i = 0; i < 4; i++)
#pragma unroll
        for (int j = 0; j < 4; j++) acc[i][j] = 0.f;

#pragma unroll 8
    for (int c = 0; c < 128; c++) {
        float4 kf = *(const float4*)&sk[c*68 + ty*4];
        float4 vf = *(const float4*)&sv[c*68 + tx*4];
        float ka[4] = {kf.x, kf.y, kf.z, kf.w};
        float va[4] = {vf.x, vf.y, vf.z, vf.w};
#pragma unroll
        for (int i = 0; i < 4; i++)
#pragma unroll
            for (int j = 0; j < 4; j++)
                acc[i][j] += ka[i] * va[j];
    }

    float* kvb = kv + (size_t)bid * (D_*D_);
#pragma unroll
    for (int i = 0; i < 4; i++) {
        float4 o = {acc[i][0], acc[i][1], acc[i][2], acc[i][3]};
        *(float4*)&kvb[(ty*4 + i) * D_ + tx*4] = o;
    }

    if (tid < D_) {
        float s = 0.f;
        for (int c = 0; c < 128; c++) s += sk[c*68 + tid];
        zk[(size_t)bid * D_ + tid] = s;
    }
}

// =================================================================
// exclusive prefix over chunks (N=16) per (b,h)
// =================================================================
__global__ __launch_bounds__(256)
void prefix_kernel(const float* __restrict__ kv, const float* __restrict__ zk,
                   float* __restrict__ S, float* __restrict__ Z)
{
    const int bh = blockIdx.x;
    const size_t base = (size_t)bh * NC * (D_*D_);
    for (int i = threadIdx.x; i < D_*D_; i += blockDim.x) {
        float run = 0.f;
        for (int n = 0; n < NC; n++) {
            S[base + (size_t)n * (D_*D_) + i] = run;
            run += kv[base + (size_t)n * (D_*D_) + i];
        }
    }
    const size_t zb = (size_t)bh * NC * D_;
    for (int i = threadIdx.x; i < D_; i += blockDim.x) {
        float run = 0.f;
        for (int n = 0; n < NC; n++) {
            Z[zb + (size_t)n * D_ + i] = run;
            run += zk[zb + (size_t)n * D_ + i];
        }
    }
}

// =================================================================
// intra-chunk attention (unchanged, passing)
// =================================================================
#define ATTN_SMEM_FLOATS 38336
__global__ __launch_bounds__(256)
void attn_kernel(const float* __restrict__ q, const float* __restrict__ k,
                 const float* __restrict__ v, const float* __restrict__ S,
                 const float* __restrict__ Z, float* __restrict__ y)
{
    extern __shared__ float sm[];
    float* sqT  = sm;
    float* skv  = sm + 8192;
    float* sAT  = sm + 16896;
    float* sS   = sm + 33792;
    float* sZ   = sm + 38144;
    float* sden = sm + 38208;

    const int bid = blockIdx.x;
    const int n = bid % NC;
    const int h = (bid / NC) % H_;
    const int b = bid / (NC * H_);
    const int tid = threadIdx.x, tx = tid & 15, ty = tid >> 4;

    const float* qb = q + (size_t)(b*T_ + n*CH) * E_ + h*D_;
    const float* kb = k + (size_t)(b*T_ + n*CH) * E_ + h*D_;
    const float* vb = v + (size_t)(b*T_ + n*CH) * E_ + h*D_;
    const float* Sb = S + (size_t)bid * (D_*D_);
    const float* Zb = Z + (size_t)bid * D_;

#pragma unroll
    for (int it = 0; it < 8; it++) {
        int idx4 = tid + it * 256;
        int c  = idx4 >> 4;
        int d0 = (idx4 & 15) << 2;
        float4 vq = *(const float4*)&qb[(size_t)c * E_ + d0];
        sqT[(d0+0)*128 + c] = vq.x;
        sqT[(d0+1)*128 + c] = vq.y;
        sqT[(d0+2)*128 + c] = vq.z;
        sqT[(d0+3)*128 + c] = vq.w;
        float4 vk = *(const float4*)&kb[(size_t)c * E_ + d0];
        skv[(d0+0)*128 + c] = vk.x;
        skv[(d0+1)*128 + c] = vk.y;
        skv[(d0+2)*128 + c] = vk.z;
        skv[(d0+3)*128 + c] = vk.w;
    }
    __syncthreads();

    float acc[8][8];
#pragma unroll
    for (int i = 0; i < 8; i++)
#pragma unroll
        for (int j = 0; j < 8; j++) acc[i][j] = 0.f;

#pragma unroll 8
    for (int kk = 0; kk < 64; kk++) {
        float af[8], bf[8];
        *(float4*)&af[0] = *(const float4*)&sqT[kk*128 + ty*8];
        *(float4*)&af[4] = *(const float4*)&sqT[kk*128 + ty*8 + 4];
        *(float4*)&bf[0] = *(const float4*)&skv[kk*128 + tx*8];
        *(float4*)&bf[4] = *(const float4*)&skv[kk*128 + tx*8 + 4];
#pragma unroll
        for (int i = 0; i < 8; i++)
#pragma unroll
            for (int j = 0; j < 8; j++)
                acc[i][j] += af[i] * bf[j];
    }

    const int c0 = ty*8, s0 = tx*8;
#pragma unroll
    for (int j = 0; j < 8; j++) {
        int s = s0 + j;
#pragma unroll
        for (int i = 0; i < 8; i++)
            if (s > c0 + i) acc[i][j] = 0.f;
        float4 t0 = {acc[0][j], acc[1][j], acc[2][j], acc[3][j]};
        *(float4*)&sAT[s*132 + c0] = t0;
        float4 t1 = {acc[4][j], acc[5][j], acc[6][j], acc[7][j]};
        *(float4*)&sAT[s*132 + c0 + 4] = t1;
    }
    __syncthreads();

#pragma unroll
    for (int it = 0; it < 8; it++) {
        int idx4 = tid + it * 256;
        int c  = idx4 >> 4;
        int e0 = (idx4 & 15) << 2;
        *(float4*)&skv[c*68 + e0] = *(const float4*)&vb[(size_t)c * E_ + e0];
    }
#pragma unroll
    for (int it = 0; it < 4; it++) {
        int idx4 = tid + it * 256;
        int d  = idx4 >> 4;
        int e0 = (idx4 & 15) << 2;
        *(float4*)&sS[d*68 + e0] = *(const float4*)&Sb[d*D_ + e0];
    }
    if (tid < 16)
        *(float4*)&sZ[tid*4] = *(const float4*)&Zb[tid*4];
    __syncthreads();

    if (tid < 128) {
        float s = EPS;
        for (int ss = 0; ss < 128; ss++) s += sAT[ss*132 + tid];
        for (int d = 0; d < 64; d++)     s += sqT[d*128 + tid] * sZ[d];
        sden[tid] = s;
    }
    __syncthreads();

    float num[8][4];
#pragma unroll
    for (int i = 0; i < 8; i++)
#pragma unroll
        for (int j = 0; j < 4; j++) num[i][j] = 0.f;

#pragma unroll 8
    for (int ss = 0; ss < 128; ss++) {
        float af[8];
        *(float4*)&af[0] = *(const float4*)&sAT[ss*132 + ty*8];
        *(float4*)&af[4] = *(const float4*)&sAT[ss*132 + ty*8 + 4];
        float4 vf = *(const float4*)&skv[ss*68 + tx*4];
        float vv[4] = {vf.x, vf.y, vf.z, vf.w};
#pragma unroll
        for (int i = 0; i < 8; i++)
#pragma unroll
            for (int j = 0; j < 4; j++)
                num[i][j] += af[i] * vv[j];
    }
#pragma unroll 8
    for (int d = 0; d < 64; d++) {
        float af[8];
        *(float4*)&af[0] = *(const float4*)&sqT[d*128 + ty*8];
        *(float4*)&af[4] = *(const float4*)&sqT[d*128 + ty*8 + 4];
        float4 sf = *(const float4*)&sS[d*68 + tx*4];
        float svv[4] = {sf.x, sf.y, sf.z, sf.w};
#pragma unroll
        for (int i = 0; i < 8; i++)
#pragma unroll
            for (int j = 0; j < 4; j++)
                num[i][j] += af[i] * svv[j];
    }

    float* yb = y + (size_t)(b*T_ + n*CH) * E_ + h*D_;
#pragma unroll
    for (int i = 0; i < 8; i++) {
        int c = ty*8 + i;
        float inv = 1.f / sden[c];
        float4 o = {num[i][0]*inv, num[i][1]*inv, num[i][2]*inv, num[i][3]*inv};
        *(float4*)&yb[(size_t)c * E_ + tx*4] = o;
    }
}

// =================================================================
extern "C" void kernel_launch(void* const* d_in, const int* in_sizes, int n_in,
                              void* d_out, int out_size)
{
    const float* x  = (const float*)d_in[0];
    const float* Wq = (const float*)d_in[1];
    const float* Wk = (const float*)d_in[2];
    const float* Wv = (const float*)d_in[3];
    const float* Wp = (const float*)d_in[4];
    const float* bp = (const float*)d_in[5];
    float* out = (float*)d_out;

    float *q, *k, *v, *y, *kv, *zk, *S, *Z;
    cudaGetSymbolAddress((void**)&q,  g_q);
    cudaGetSymbolAddress((void**)&k,  g_k);
    cudaGetSymbolAddress((void**)&v,  g_v);
    cudaGetSymbolAddress((void**)&y,  g_y);
    cudaGetSymbolAddress((void**)&kv, g_kv);
    cudaGetSymbolAddress((void**)&zk, g_zk);
    cudaGetSymbolAddress((void**)&S,  g_S);
    cudaGetSymbolAddress((void**)&Z,  g_Z);

    const int kv_smem   = 2 * 128 * 68 * (int)sizeof(float);
    const int attn_smem = ATTN_SMEM_FLOATS * (int)sizeof(float);
    cudaFuncSetAttribute(kv_kernel,   cudaFuncAttributeMaxDynamicSharedMemorySize, kv_smem);
    cudaFuncSetAttribute(attn_kernel, cudaFuncAttributeMaxDynamicSharedMemorySize, attn_smem);
    cudaFuncSetAttribute(tc_gemm<1,0>, cudaFuncAttributeMaxDynamicSharedMemorySize, GEMM_SMEM);
    cudaFuncSetAttribute(tc_gemm<0,0>, cudaFuncAttributeMaxDynamicSharedMemorySize, GEMM_SMEM);
    cudaFuncSetAttribute(tc_gemm<0,1>, cudaFuncAttributeMaxDynamicSharedMemorySize, GEMM_SMEM);

    dim3 blk(256);
    dim3 gg(E_/TN, M_/TM);   // (8, 64)

    tc_gemm<1,0><<<gg, blk, GEMM_SMEM>>>(x, Wq, nullptr, q, M_, E_, E_);
    tc_gemm<1,0><<<gg, blk, GEMM_SMEM>>>(x, Wk, nullptr, k, M_, E_, E_);
    tc_gemm<0,0><<<gg, blk, GEMM_SMEM>>>(x, Wv, nullptr, v, M_, E_, E_);

    kv_kernel<<<B_*H_*NC, blk, kv_smem>>>(k, v, kv, zk);
    prefix_kernel<<<B_*H_, blk>>>(kv, zk, S, Z);
    attn_kernel<<<B_*H_*NC, blk, attn_smem>>>(q, k, v, S, Z, y);

    tc_gemm<0,1><<<gg, blk, GEMM_SMEM>>>(y, Wp, bp, out, M_, E_, E_);
}